// round 1
// baseline (speedup 1.0000x reference)
#include <cuda_runtime.h>
#include <cuda_bf16.h>
#include <cstdint>

// Problem constants
#define Bb 2
#define Hh 8
#define Tt 2048
#define Dd 512
#define BHn (Bb*Hh)

#define QKV_ELEMS (16777216u)   // BH*T*D
#define S_ELEMS   (67108864u)   // BH*T*T

// ---------------- scratch (device globals; no runtime allocation) ----------------
__device__ __nv_bfloat162 g_Qg[QKV_ELEMS];   // (Q * gate / 8) split hi/lo
__device__ __nv_bfloat162 g_K [QKV_ELEMS];   // K split hi/lo
__device__ __nv_bfloat162 g_Vt[QKV_ELEMS];   // V transposed [bh][d][t] split hi/lo
__device__ float          g_S [S_ELEMS];     // logits, then overwritten in-place by P (bf16x2)

// ---------------- helpers ----------------
__device__ __forceinline__ __nv_bfloat162 split2(float x) {
    __nv_bfloat16 h = __float2bfloat16(x);
    float lo = x - __bfloat162float(h);
    __nv_bfloat162 r;
    r.x = h;
    r.y = __float2bfloat16(lo);
    return r;
}

__device__ __forceinline__ void ldm4(unsigned* r, const void* p) {
    unsigned a = (unsigned)__cvta_generic_to_shared(p);
    asm volatile("ldmatrix.sync.aligned.m8n8.x4.shared.b16 {%0,%1,%2,%3}, [%4];"
                 : "=r"(r[0]), "=r"(r[1]), "=r"(r[2]), "=r"(r[3]) : "r"(a));
}

__device__ __forceinline__ void mma16816(float* c, const unsigned* a, unsigned b0, unsigned b1) {
    asm volatile(
        "mma.sync.aligned.m16n8k16.row.col.f32.bf16.bf16.f32 "
        "{%0,%1,%2,%3},{%4,%5,%6,%7},{%8,%9},{%0,%1,%2,%3};\n"
        : "+f"(c[0]), "+f"(c[1]), "+f"(c[2]), "+f"(c[3])
        : "r"(a[0]), "r"(a[1]), "r"(a[2]), "r"(a[3]), "r"(b0), "r"(b1));
}

// ---------------- convert Q,K ----------------
__global__ void convert_qk_kernel(const float* __restrict__ Q,
                                  const float* __restrict__ K,
                                  const float* __restrict__ route) {
    unsigned i = blockIdx.x * 256u + threadIdx.x;      // 0 .. 16777215
    int d = (int)(i & (Dd - 1));
    int b = (int)(i >> 23);                            // H*T*D = 2^23
    float g = route[b * 8 + (d >> 6)] * 0.125f;        // gate * 1/sqrt(64)
    g_Qg[i] = split2(Q[i] * g);
    g_K[i]  = split2(K[i]);
}

// ---------------- transpose + convert V ----------------
__global__ void convert_vt_kernel(const float* __restrict__ V) {
    __shared__ float tile[32][33];
    int bh = blockIdx.z;
    int t0 = blockIdx.x * 32;
    int d0 = blockIdx.y * 32;
    int tx = threadIdx.x & 31, ty = threadIdx.x >> 5;  // 32 x 8
    const float* Vb = V + (size_t)bh * Tt * Dd;
#pragma unroll
    for (int j = 0; j < 4; j++) {
        int tt = t0 + ty + j * 8;
        tile[ty + j * 8][tx] = Vb[(size_t)tt * Dd + d0 + tx];
    }
    __syncthreads();
#pragma unroll
    for (int j = 0; j < 4; j++) {
        int d = d0 + ty + j * 8;
        int tt = t0 + tx;
        g_Vt[(size_t)bh * Dd * Tt + (size_t)d * Tt + tt] = split2(tile[tx][ty + j * 8]);
    }
}

// ---------------- NT split-bf16 GEMM (used twice) ----------------
// EPI==0:  S[2048,2048] = Qg[2048,512] * K[2048,512]^T      (fp32 out to g_S)
// EPI==1:  out[2048,512] = P[2048,2048] * Vt[512,2048]^T     (*gate, fp32 out)
template<int EPI>
__global__ __launch_bounds__(256) void gemm_nt(float* __restrict__ outp,
                                               const float* __restrict__ route) {
    constexpr int Kd  = EPI ? Tt : Dd;
    constexpr int lda = EPI ? Tt : Dd;
    constexpr int ldb = EPI ? Tt : Dd;
    constexpr int ldc = EPI ? Dd : Tt;

    const int bh = blockIdx.z;
    const __nv_bfloat162* Abase = EPI ? (const __nv_bfloat162*)g_S + (size_t)bh * Tt * Tt
                                      : g_Qg + (size_t)bh * Tt * Dd;
    const __nv_bfloat162* Bbase = EPI ? g_Vt + (size_t)bh * Dd * Tt
                                      : g_K  + (size_t)bh * Tt * Dd;
    const __nv_bfloat162* Ab = Abase + (size_t)blockIdx.y * 128 * lda;
    const __nv_bfloat162* Bp = Bbase + (size_t)blockIdx.x * 64  * ldb;

    __shared__ __align__(16) unsigned short sAh[128 * 40];
    __shared__ __align__(16) unsigned short sAl[128 * 40];
    __shared__ __align__(16) unsigned short sBh[64 * 40];
    __shared__ __align__(16) unsigned short sBl[64 * 40];

    const int t = threadIdx.x;
    const int lane = t & 31, warp = t >> 5;
    const int wm = warp >> 1, wn = warp & 1;       // 4 x 2 warp grid, warp tile 32x32
    const int lrow = lane & 15;
    const int lko  = (lane >> 4) << 3;

    float acc[2][4][4];
#pragma unroll
    for (int a = 0; a < 2; a++)
#pragma unroll
        for (int b = 0; b < 4; b++)
#pragma unroll
            for (int c = 0; c < 4; c++) acc[a][b][c] = 0.f;

    const int arow = t >> 3;           // 0..31
    const int acol = (t & 7) * 4;      // bf162-element col within 32-wide chunk

    for (int k0 = 0; k0 < Kd; k0 += 32) {
        // ---- global -> shared (unpack hi/lo planes) ----
#pragma unroll
        for (int j = 0; j < 4; j++) {
            int m = arow + j * 32;
            uint4 v = *(const uint4*)(Ab + (size_t)m * lda + k0 + acol);
            unsigned hi01 = (v.x & 0xFFFFu) | (v.y << 16);
            unsigned lo01 = (v.x >> 16)     | (v.y & 0xFFFF0000u);
            unsigned hi23 = (v.z & 0xFFFFu) | (v.w << 16);
            unsigned lo23 = (v.z >> 16)     | (v.w & 0xFFFF0000u);
            *(uint2*)&sAh[m * 40 + acol] = make_uint2(hi01, hi23);
            *(uint2*)&sAl[m * 40 + acol] = make_uint2(lo01, lo23);
        }
#pragma unroll
        for (int j = 0; j < 2; j++) {
            int n = arow + j * 32;
            uint4 v = *(const uint4*)(Bp + (size_t)n * ldb + k0 + acol);
            unsigned hi01 = (v.x & 0xFFFFu) | (v.y << 16);
            unsigned lo01 = (v.x >> 16)     | (v.y & 0xFFFF0000u);
            unsigned hi23 = (v.z & 0xFFFFu) | (v.w << 16);
            unsigned lo23 = (v.z >> 16)     | (v.w & 0xFFFF0000u);
            *(uint2*)&sBh[n * 40 + acol] = make_uint2(hi01, hi23);
            *(uint2*)&sBl[n * 40 + acol] = make_uint2(lo01, lo23);
        }
        __syncthreads();

        // ---- two k16 steps of MMA ----
#pragma unroll
        for (int ks = 0; ks < 2; ks++) {
            int kb = ks * 16 + lko;
            unsigned ah[2][4], al[2][4], bhr[2][4], blr[2][4];
#pragma unroll
            for (int mt = 0; mt < 2; mt++) {
                int r = (wm * 32 + mt * 16 + lrow) * 40 + kb;
                ldm4(ah[mt], &sAh[r]);
                ldm4(al[mt], &sAl[r]);
            }
#pragma unroll
            for (int nb = 0; nb < 2; nb++) {
                int r = (wn * 32 + nb * 16 + lrow) * 40 + kb;
                ldm4(bhr[nb], &sBh[r]);
                ldm4(blr[nb], &sBl[r]);
            }
#pragma unroll
            for (int mt = 0; mt < 2; mt++)
#pragma unroll
                for (int nt = 0; nt < 4; nt++) {
                    int nb = nt >> 1, o = nt & 1;
                    // split-3: hi*hi + hi*lo + lo*hi
                    mma16816(acc[mt][nt], ah[mt], bhr[nb][o], bhr[nb][o + 2]);
                    mma16816(acc[mt][nt], ah[mt], blr[nb][o], blr[nb][o + 2]);
                    mma16816(acc[mt][nt], al[mt], bhr[nb][o], bhr[nb][o + 2]);
                }
        }
        __syncthreads();
    }

    // ---- epilogue ----
    float* Cp = EPI ? (outp + (size_t)bh * Tt * Dd)
                    : (g_S + (size_t)bh * Tt * Tt);
    int rbase = blockIdx.y * 128 + wm * 32 + (lane >> 2);
    int cbase = blockIdx.x * 64  + wn * 32 + (lane & 3) * 2;
#pragma unroll
    for (int mt = 0; mt < 2; mt++)
#pragma unroll
        for (int nt = 0; nt < 4; nt++) {
            int r = rbase + mt * 16;
            int c = cbase + nt * 8;
            float s = 1.f;
            if (EPI) s = route[(bh >> 3) * 8 + (c >> 6)];   // gate on output channel
            float2 v0 = make_float2(acc[mt][nt][0] * s, acc[mt][nt][1] * s);
            float2 v1 = make_float2(acc[mt][nt][2] * s, acc[mt][nt][3] * s);
            *(float2*)&Cp[(size_t)r       * ldc + c] = v0;
            *(float2*)&Cp[(size_t)(r + 8) * ldc + c] = v1;
        }
}

// ---------------- masked row softmax (in-place: fp32 S -> bf16x2 P) ----------------
__global__ __launch_bounds__(256) void softmax_rows(const int* __restrict__ mask) {
    int row = blockIdx.x;             // bh*T + q, 0..32767
    int q = row & (Tt - 1);
    float* Srow = g_S + (size_t)row * Tt;
    const int* mrow = mask + (size_t)q * Tt;
    int t = threadIdx.x;
    int lane = t & 31, warp = t >> 5;

    float s[8];
#pragma unroll
    for (int j = 0; j < 8; j++) {
        int k = t + j * 256;
        s[j] = mrow[k] ? -INFINITY : Srow[k];
    }

    // block max
    float mx = s[0];
#pragma unroll
    for (int j = 1; j < 8; j++) mx = fmaxf(mx, s[j]);
#pragma unroll
    for (int o = 16; o; o >>= 1) mx = fmaxf(mx, __shfl_xor_sync(0xFFFFFFFFu, mx, o));
    __shared__ float red[8];
    if (lane == 0) red[warp] = mx;
    __syncthreads();
    float mall = red[0];
#pragma unroll
    for (int w = 1; w < 8; w++) mall = fmaxf(mall, red[w]);

    // exp + block sum
    float e[8];
    float sum = 0.f;
#pragma unroll
    for (int j = 0; j < 8; j++) {
        e[j] = (s[j] == -INFINITY) ? 0.f : expf(s[j] - mall);
        sum += e[j];
    }
#pragma unroll
    for (int o = 16; o; o >>= 1) sum += __shfl_xor_sync(0xFFFFFFFFu, sum, o);
    __syncthreads();                   // done reading red for max
    if (lane == 0) red[warp] = sum;
    __syncthreads();
    float tot = 0.f;
#pragma unroll
    for (int w = 0; w < 8; w++) tot += red[w];
    float inv = tot > 0.f ? 1.f / tot : 0.f;

    __nv_bfloat162* Prow = (__nv_bfloat162*)Srow;
#pragma unroll
    for (int j = 0; j < 8; j++) {
        int k = t + j * 256;
        Prow[k] = split2(e[j] * inv);
    }
}

// ---------------- launch ----------------
extern "C" void kernel_launch(void* const* d_in, const int* in_sizes, int n_in,
                              void* d_out, int out_size) {
    const float* Q     = (const float*)d_in[0];
    const float* K     = (const float*)d_in[1];
    const float* V     = (const float*)d_in[2];
    const float* route = (const float*)d_in[3];
    // d_in[4] = ids (unused by reference)
    const int*   mask  = (const int*)d_in[5];
    float* out = (float*)d_out;

    convert_qk_kernel<<<QKV_ELEMS / 256, 256>>>(Q, K, route);
    convert_vt_kernel<<<dim3(Tt / 32, Dd / 32, BHn), 256>>>(V);
    gemm_nt<0><<<dim3(Tt / 64, Tt / 128, BHn), 256>>>(nullptr, route);
    softmax_rows<<<BHn * Tt, 256>>>(mask);
    gemm_nt<1><<<dim3(Dd / 64, Tt / 128, BHn), 256>>>(out, route);
}